// round 5
// baseline (speedup 1.0000x reference)
#include <cuda_runtime.h>
#include <cuda_bf16.h>
#include <cstdint>

typedef __nv_bfloat16 bf16;

#define BATCH 16384
#define TT    10
#define FF    34
#define HH    256
#define NG    1024
#define KK    512

#define PITCH 40
#define TILE_ELEMS (128 * PITCH)
#define SMEM_CELL (2 * 4 * TILE_ELEMS * 2)     // 81920 B
#define SMEM_DEC  ((64 * 260 + 34 * 260) * 4)  // 101920 B

// ---------- scratch (device globals; allocation is forbidden) ----------
__device__ bf16  g_enc_hi[BATCH * TT * HH];
__device__ bf16  g_enc_lo[BATCH * TT * HH];
__device__ bf16  g_h1_hi[2][BATCH * HH];
__device__ bf16  g_h1_lo[2][BATCH * HH];
__device__ bf16  g_h2_hi[2][BATCH * HH];
__device__ bf16  g_h2_lo[2][BATCH * HH];
__device__ float g_c1[BATCH * HH];
__device__ float g_c2[BATCH * HH];
__device__ float g_pred[BATCH * TT * HH];
__device__ bf16  g_W1_hi[NG * KK];
__device__ bf16  g_W1_lo[NG * KK];
__device__ bf16  g_W2_hi[NG * KK];
__device__ bf16  g_W2_lo[NG * KK];
__device__ float g_bias1[NG];
__device__ float g_bias2[NG];

// ---------- helpers ----------
__device__ __forceinline__ void cp16(void* sptr, const void* gptr) {
    uint32_t s = (uint32_t)__cvta_generic_to_shared(sptr);
    asm volatile("cp.async.cg.shared.global [%0], [%1], 16;\n" :: "r"(s), "l"(gptr));
}
__device__ __forceinline__ void cp_commit() { asm volatile("cp.async.commit_group;\n" ::); }
__device__ __forceinline__ void cp_wait1()  { asm volatile("cp.async.wait_group 1;\n" ::); }
__device__ __forceinline__ void cp_wait0()  { asm volatile("cp.async.wait_group 0;\n" ::); }

__device__ __forceinline__ void ldsm4(uint32_t& r0, uint32_t& r1, uint32_t& r2, uint32_t& r3,
                                      const void* p) {
    uint32_t a = (uint32_t)__cvta_generic_to_shared(p);
    asm volatile("ldmatrix.sync.aligned.m8n8.x4.shared.b16 {%0,%1,%2,%3}, [%4];\n"
                 : "=r"(r0), "=r"(r1), "=r"(r2), "=r"(r3) : "r"(a));
}
__device__ __forceinline__ void mma16816(float* d, const uint32_t* a, const uint32_t* b) {
    asm volatile("mma.sync.aligned.m16n8k16.row.col.f32.bf16.bf16.f32 "
                 "{%0,%1,%2,%3}, {%4,%5,%6,%7}, {%8,%9}, {%0,%1,%2,%3};\n"
                 : "+f"(d[0]), "+f"(d[1]), "+f"(d[2]), "+f"(d[3])
                 : "r"(a[0]), "r"(a[1]), "r"(a[2]), "r"(a[3]), "r"(b[0]), "r"(b[1]));
}
__device__ __forceinline__ float fsig(float x)  { return 1.f / (1.f + __expf(-x)); }
__device__ __forceinline__ float ftanh(float x) { return 2.f / (1.f + __expf(-2.f * x)) - 1.f; }

// ---------- init / prep ----------
__global__ void zero_state_kernel() {
    int idx = blockIdx.x * blockDim.x + threadIdx.x;
    if (idx < BATCH * HH) {
        g_c1[idx] = 0.f; g_c2[idx] = 0.f;
        bf16 z = __float2bfloat16(0.f);
        g_h1_hi[0][idx] = z; g_h1_lo[0][idx] = z;
        g_h2_hi[0][idx] = z; g_h2_lo[0][idx] = z;
    }
}

__global__ void prep_kernel(const float* __restrict__ Wih1, const float* __restrict__ Whh1,
                            const float* __restrict__ bih1, const float* __restrict__ bhh1,
                            const float* __restrict__ Wih2, const float* __restrict__ Whh2,
                            const float* __restrict__ bih2, const float* __restrict__ bhh2) {
    int idx = blockIdx.x * blockDim.x + threadIdx.x;
    if (idx < NG * KK) {
        int r = idx >> 9, k = idx & 511;
        float w1 = (k < 256) ? Wih1[r * 256 + k] : Whh1[r * 256 + (k - 256)];
        bf16 h1 = __float2bfloat16(w1);
        g_W1_hi[idx] = h1;
        g_W1_lo[idx] = __float2bfloat16(w1 - __bfloat162float(h1));
        float w2 = (k < 256) ? Wih2[r * 256 + k] : Whh2[r * 256 + (k - 256)];
        bf16 h2 = __float2bfloat16(w2);
        g_W2_hi[idx] = h2;
        g_W2_lo[idx] = __float2bfloat16(w2 - __bfloat162float(h2));
    }
    if (idx < NG) {
        g_bias1[idx] = bih1[idx] + bhh1[idx];
        g_bias2[idx] = bih2[idx] + bhh2[idx];
    }
}

// ---------- encode: enc = x @ W_enc^T + b_enc (rows of flattened [B*T]) ----------
__global__ void encode_kernel(const float* __restrict__ x, const float* __restrict__ W,
                              const float* __restrict__ b) {
    __shared__ float Ws[FF][HH];
    __shared__ float xs[32][FF];
    int tid = threadIdx.x;
    for (int idx = tid; idx < HH * FF; idx += 256) {
        int e = idx / FF, f = idx % FF;
        Ws[f][e] = W[idx];
    }
    long r0 = (long)blockIdx.x * 32;
    for (int idx = tid; idx < 32 * FF; idx += 256) {
        int r = idx / FF, f = idx % FF;
        xs[r][f] = x[(r0 + r) * FF + f];
    }
    __syncthreads();
    float be = b[tid];
    float acc[32];
    #pragma unroll
    for (int r = 0; r < 32; ++r) acc[r] = be;
    #pragma unroll
    for (int f = 0; f < FF; ++f) {
        float w = Ws[f][tid];
        #pragma unroll
        for (int r = 0; r < 32; ++r) acc[r] += xs[r][f] * w;
    }
    #pragma unroll
    for (int r = 0; r < 32; ++r) {
        long o = (r0 + r) * HH + tid;
        bf16 hi = __float2bfloat16(acc[r]);
        g_enc_hi[o] = hi;
        g_enc_lo[o] = __float2bfloat16(acc[r] - __bfloat162float(hi));
    }
}

// ---------- fused LSTM cell ----------
__device__ __forceinline__ void cell_load(bf16* sb, int stage, int chunk, int tid,
                                          int m0, int u0,
                                          const bf16* Xhi, const bf16* Xlo, int xStride,
                                          const bf16* Hhi, const bf16* Hlo,
                                          const bf16* Whi, const bf16* Wlo) {
    bf16* sAhi = sb + stage * 4 * TILE_ELEMS;
    bf16* sAlo = sAhi + TILE_ELEMS;
    bf16* sBhi = sAlo + TILE_ELEMS;
    bf16* sBlo = sBhi + TILE_ELEMS;
    #pragma unroll
    for (int i = 0; i < 2; ++i) {
        int seg = tid + (i << 8);
        int r   = seg >> 2;
        int ko  = (seg & 3) << 3;
        int kg  = (chunk << 5) + ko;
        int so  = r * PITCH + ko;
        const bf16 *ghi, *glo;
        if (kg < 256) {
            long off = (long)(m0 + r) * xStride + kg;
            ghi = Xhi + off; glo = Xlo + off;
        } else {
            long off = (long)(m0 + r) * HH + (kg - 256);
            ghi = Hhi + off; glo = Hlo + off;
        }
        cp16(sAhi + so, ghi);
        cp16(sAlo + so, glo);
        int wr = ((r >> 5) << 8) + u0 + (r & 31);
        long woff = (long)wr * KK + kg;
        cp16(sBhi + so, Whi + woff);
        cp16(sBlo + so, Wlo + woff);
    }
}

__device__ __forceinline__ void cell_compute(bf16* sb, int stage, int wm, int wn, int lane,
                                             float acc[2][8][4]) {
    bf16* sAhi = sb + stage * 4 * TILE_ELEMS;
    bf16* sAlo = sAhi + TILE_ELEMS;
    bf16* sBhi = sAlo + TILE_ELEMS;
    bf16* sBlo = sBhi + TILE_ELEMS;
    #pragma unroll
    for (int ks = 0; ks < 2; ++ks) {
        uint32_t ah[2][4], al[2][4], bh[8][2], bl[8][2];
        #pragma unroll
        for (int mt = 0; mt < 2; ++mt) {
            int row = wm * 32 + mt * 16 + (lane & 15);
            int col = ks * 16 + ((lane >> 4) << 3);
            int o = row * PITCH + col;
            ldsm4(ah[mt][0], ah[mt][1], ah[mt][2], ah[mt][3], sAhi + o);
            ldsm4(al[mt][0], al[mt][1], al[mt][2], al[mt][3], sAlo + o);
        }
        #pragma unroll
        for (int np = 0; np < 4; ++np) {
            int row = wn * 64 + np * 16 + ((lane >> 4) << 3) + (lane & 7);
            int col = ks * 16 + (((lane >> 3) & 1) << 3);
            int o = row * PITCH + col;
            ldsm4(bh[2 * np][0], bh[2 * np][1], bh[2 * np + 1][0], bh[2 * np + 1][1], sBhi + o);
            ldsm4(bl[2 * np][0], bl[2 * np][1], bl[2 * np + 1][0], bl[2 * np + 1][1], sBlo + o);
        }
        #pragma unroll
        for (int mt = 0; mt < 2; ++mt)
            #pragma unroll
            for (int nt = 0; nt < 8; ++nt) {
                mma16816(acc[mt][nt], ah[mt], bh[nt]);
                mma16816(acc[mt][nt], ah[mt], bl[nt]);
                mma16816(acc[mt][nt], al[mt], bh[nt]);
            }
    }
}

__global__ void __launch_bounds__(256, 1)
cell_kernel(int layer, int xKind, int xIdx, int hIdx, int outIdx, int slot) {
    extern __shared__ __align__(16) char smem_raw[];
    bf16* sb = (bf16*)smem_raw;
    const int tid  = threadIdx.x;
    const int m0   = blockIdx.x * 128;
    const int u0   = blockIdx.y * 32;
    const int lane = tid & 31;
    const int wm   = (tid >> 5) & 3;
    const int wn   = tid >> 7;

    const bf16 *Whi, *Wlo, *Hhi, *Hlo;
    bf16 *HoHi, *HoLo;
    const float* bias;
    float* cSt;
    if (layer == 1) {
        Whi = g_W1_hi; Wlo = g_W1_lo; bias = g_bias1; cSt = g_c1;
        Hhi = g_h1_hi[hIdx]; Hlo = g_h1_lo[hIdx];
        HoHi = g_h1_hi[outIdx]; HoLo = g_h1_lo[outIdx];
    } else {
        Whi = g_W2_hi; Wlo = g_W2_lo; bias = g_bias2; cSt = g_c2;
        Hhi = g_h2_hi[hIdx]; Hlo = g_h2_lo[hIdx];
        HoHi = g_h2_hi[outIdx]; HoLo = g_h2_lo[outIdx];
    }
    const bf16 *Xhi, *Xlo;
    int xStride;
    if (xKind == 0)      { Xhi = g_enc_hi + xIdx * HH; Xlo = g_enc_lo + xIdx * HH; xStride = TT * HH; }
    else if (xKind == 1) { Xhi = g_h1_hi[xIdx]; Xlo = g_h1_lo[xIdx]; xStride = HH; }
    else                 { Xhi = g_h2_hi[xIdx]; Xlo = g_h2_lo[xIdx]; xStride = HH; }

    float acc[2][8][4];
    #pragma unroll
    for (int a = 0; a < 2; ++a)
        #pragma unroll
        for (int b = 0; b < 8; ++b)
            #pragma unroll
            for (int c = 0; c < 4; ++c) acc[a][b][c] = 0.f;

    cell_load(sb, 0, 0, tid, m0, u0, Xhi, Xlo, xStride, Hhi, Hlo, Whi, Wlo);
    cp_commit();

    int cs = 0;
    #pragma unroll 1
    for (int ch = 0; ch < 16; ++ch) {
        if (ch + 1 < 16) {
            cell_load(sb, cs ^ 1, ch + 1, tid, m0, u0, Xhi, Xlo, xStride, Hhi, Hlo, Whi, Wlo);
            cp_commit();
            cp_wait1();
        } else {
            cp_wait0();
        }
        __syncthreads();
        cell_compute(sb, cs, wm, wn, lane, acc);
        __syncthreads();
        cs ^= 1;
    }

    // epilogue: accumulators -> smem -> LSTM nonlinearity
    float* sAcc = (float*)sb;
    const int PA = 132;
    #pragma unroll
    for (int mt = 0; mt < 2; ++mt)
        #pragma unroll
        for (int nt = 0; nt < 8; ++nt) {
            int row = wm * 32 + mt * 16 + (lane >> 2);
            int col = wn * 64 + nt * 8 + ((lane & 3) << 1);
            *(float2*)&sAcc[row * PA + col]       = make_float2(acc[mt][nt][0], acc[mt][nt][1]);
            *(float2*)&sAcc[(row + 8) * PA + col] = make_float2(acc[mt][nt][2], acc[mt][nt][3]);
        }
    __syncthreads();

    for (int idx = tid; idx < 128 * 32; idx += 256) {
        int row = idx >> 5, u = idx & 31;
        float iv = sAcc[row * PA + u]       + bias[u0 + u];
        float fv = sAcc[row * PA + 32 + u]  + bias[256 + u0 + u];
        float gv = sAcc[row * PA + 64 + u]  + bias[512 + u0 + u];
        float ov = sAcc[row * PA + 96 + u]  + bias[768 + u0 + u];
        long gi = (long)(m0 + row) * HH + u0 + u;
        float c = fsig(fv) * cSt[gi] + fsig(iv) * ftanh(gv);
        cSt[gi] = c;
        float h = fsig(ov) * ftanh(c);
        bf16 hh = __float2bfloat16(h);
        HoHi[gi] = hh;
        HoLo[gi] = __float2bfloat16(h - __bfloat162float(hh));
        if (slot >= 0)
            g_pred[((long)(m0 + row) * TT + slot) * HH + u0 + u] = h;
    }
}

// ---------- decode + cumsum + residual ----------
__global__ void dec_kernel(const float* __restrict__ x, const float* __restrict__ Wdec,
                           const float* __restrict__ bdec, float* __restrict__ out) {
    extern __shared__ float sm[];
    float* sP = sm;              // [64][260]
    float* sW = sm + 64 * 260;   // [34][260]
    int tid = threadIdx.x;
    long b0 = (long)blockIdx.x * 64;

    for (int i = tid; i < 34 * 64; i += 288) {
        int f = i / 64, k4 = i % 64;
        reinterpret_cast<float4*>(sW + f * 260)[k4] =
            reinterpret_cast<const float4*>(Wdec + f * 256)[k4];
    }

    int a = tid;
    bool act = a < 272;
    int rg = a & 15, fp = a >> 4;       // rg: 4-row group, fp: f pair (0..16)
    int f0 = fp * 2;
    float acc[4][2];
    float bd0 = 0.f, bd1 = 0.f;
    if (act) {
        bd0 = bdec[f0]; bd1 = bdec[f0 + 1];
        #pragma unroll
        for (int i = 0; i < 4; ++i) {
            long b = b0 + rg * 4 + i;
            acc[i][0] = x[b * (TT * FF) + 9 * FF + f0];
            acc[i][1] = x[b * (TT * FF) + 9 * FF + f0 + 1];
        }
    }

    #pragma unroll 1
    for (int j = 0; j < TT; ++j) {
        __syncthreads();
        for (int i = tid; i < 64 * 64; i += 288) {
            int r = i >> 6, k4 = i & 63;
            reinterpret_cast<float4*>(sP + r * 260)[k4] =
                reinterpret_cast<const float4*>(g_pred + (b0 + r) * (TT * HH) + j * HH)[k4];
        }
        __syncthreads();
        if (act) {
            float s[4][2] = {{0.f, 0.f}, {0.f, 0.f}, {0.f, 0.f}, {0.f, 0.f}};
            #pragma unroll 4
            for (int k = 0; k < 256; k += 4) {
                float4 w0 = *reinterpret_cast<float4*>(sW + f0 * 260 + k);
                float4 w1 = *reinterpret_cast<float4*>(sW + (f0 + 1) * 260 + k);
                #pragma unroll
                for (int i = 0; i < 4; ++i) {
                    float4 p = *reinterpret_cast<float4*>(sP + (rg * 4 + i) * 260 + k);
                    s[i][0] += p.x * w0.x + p.y * w0.y + p.z * w0.z + p.w * w0.w;
                    s[i][1] += p.x * w1.x + p.y * w1.y + p.z * w1.z + p.w * w1.w;
                }
            }
            #pragma unroll
            for (int i = 0; i < 4; ++i) {
                acc[i][0] += s[i][0] + bd0;
                acc[i][1] += s[i][1] + bd1;
                long b = b0 + rg * 4 + i;
                out[b * (TT * FF) + j * FF + f0]     = acc[i][0];
                out[b * (TT * FF) + j * FF + f0 + 1] = acc[i][1];
            }
        }
    }
}

// ---------- launch ----------
extern "C" void kernel_launch(void* const* d_in, const int* in_sizes, int n_in,
                              void* d_out, int out_size) {
    const float* x     = (const float*)d_in[0];
    const float* W_enc = (const float*)d_in[1];
    const float* b_enc = (const float*)d_in[2];
    const float* Wih1  = (const float*)d_in[3];
    const float* Whh1  = (const float*)d_in[4];
    const float* bih1  = (const float*)d_in[5];
    const float* bhh1  = (const float*)d_in[6];
    const float* Wih2  = (const float*)d_in[7];
    const float* Whh2  = (const float*)d_in[8];
    const float* bih2  = (const float*)d_in[9];
    const float* bhh2  = (const float*)d_in[10];
    const float* Wdec  = (const float*)d_in[11];
    const float* bdec  = (const float*)d_in[12];
    float* out = (float*)d_out;

    cudaFuncSetAttribute(cell_kernel, cudaFuncAttributeMaxDynamicSharedMemorySize, SMEM_CELL);
    cudaFuncSetAttribute(dec_kernel,  cudaFuncAttributeMaxDynamicSharedMemorySize, SMEM_DEC);

    zero_state_kernel<<<(BATCH * HH + 255) / 256, 256>>>();
    prep_kernel<<<(NG * KK + 255) / 256, 256>>>(Wih1, Whh1, bih1, bhh1, Wih2, Whh2, bih2, bhh2);
    encode_kernel<<<(BATCH * TT) / 32, 256>>>(x, W_enc, b_enc);

    dim3 cg(BATCH / 128, HH / 32);
    int p1 = 0, p2 = 0;
    for (int t = 0; t < TT; ++t) {
        cell_kernel<<<cg, 256, SMEM_CELL>>>(1, 0, t, p1, p1 ^ 1, -1);
        p1 ^= 1;
        cell_kernel<<<cg, 256, SMEM_CELL>>>(2, 1, p1, p2, p2 ^ 1, (t == 9) ? 0 : -1);
        p2 ^= 1;
    }
    for (int s = 1; s <= 9; ++s) {
        cell_kernel<<<cg, 256, SMEM_CELL>>>(1, 2, p2, p1, p1 ^ 1, -1);
        p1 ^= 1;
        cell_kernel<<<cg, 256, SMEM_CELL>>>(2, 1, p1, p2, p2 ^ 1, s);
        p2 ^= 1;
    }
    dec_kernel<<<BATCH / 64, 288, SMEM_DEC>>>(x, Wdec, bdec, out);
}

// round 8
// speedup vs baseline: 1.1601x; 1.1601x over previous
#include <cuda_runtime.h>
#include <cuda_bf16.h>
#include <cstdint>

typedef __nv_bfloat16 bf16;

#define BATCH 16384
#define TT    10
#define FF    34
#define HH    256
#define NG    1024
#define KK    512

// cell GEMM tiling: CTA tile 128M x 128N, K-chunks of 64, 3 smem stages
#define PITCH   72                        // bf16 elems per smem row (64 data + 8 pad)
#define TILE_E  (128 * PITCH)             // elems per 128x64 tile
#define TILE_BB (TILE_E * 2)              // bytes per tile = 18432
#define STAGE_B (4 * TILE_BB)             // Ahi, Alo, Bhi, Blo = 73728
#define SMEM_CELL (3 * STAGE_B)           // 221184
#define SMEM_DEC  ((64 * 260 + 34 * 260) * 4)  // 101920

// ---------- scratch (device globals; allocation is forbidden) ----------
__device__ bf16  g_enc_hi[BATCH * TT * HH];
__device__ bf16  g_enc_lo[BATCH * TT * HH];
__device__ bf16  g_h1_hi[2][BATCH * HH];
__device__ bf16  g_h1_lo[2][BATCH * HH];
__device__ bf16  g_h2_hi[2][BATCH * HH];
__device__ bf16  g_h2_lo[2][BATCH * HH];
__device__ float g_c1[BATCH * HH];
__device__ float g_c2[BATCH * HH];
__device__ float g_pred[BATCH * TT * HH];
__device__ bf16  g_W1_hi[NG * KK];
__device__ bf16  g_W1_lo[NG * KK];
__device__ bf16  g_W2_hi[NG * KK];
__device__ bf16  g_W2_lo[NG * KK];
__device__ float g_bias1[NG];
__device__ float g_bias2[NG];

// ---------- helpers ----------
__device__ __forceinline__ void cp16(void* sptr, const void* gptr) {
    uint32_t s = (uint32_t)__cvta_generic_to_shared(sptr);
    asm volatile("cp.async.cg.shared.global [%0], [%1], 16;\n" :: "r"(s), "l"(gptr));
}
__device__ __forceinline__ void cp_commit() { asm volatile("cp.async.commit_group;\n" ::); }
__device__ __forceinline__ void cp_wait2()  { asm volatile("cp.async.wait_group 2;\n" ::); }

__device__ __forceinline__ void ldsm4(uint32_t& r0, uint32_t& r1, uint32_t& r2, uint32_t& r3,
                                      const void* p) {
    uint32_t a = (uint32_t)__cvta_generic_to_shared(p);
    asm volatile("ldmatrix.sync.aligned.m8n8.x4.shared.b16 {%0,%1,%2,%3}, [%4];\n"
                 : "=r"(r0), "=r"(r1), "=r"(r2), "=r"(r3) : "r"(a));
}
__device__ __forceinline__ void mma16816(float* d, const uint32_t* a, const uint32_t* b) {
    asm volatile("mma.sync.aligned.m16n8k16.row.col.f32.bf16.bf16.f32 "
                 "{%0,%1,%2,%3}, {%4,%5,%6,%7}, {%8,%9}, {%0,%1,%2,%3};\n"
                 : "+f"(d[0]), "+f"(d[1]), "+f"(d[2]), "+f"(d[3])
                 : "r"(a[0]), "r"(a[1]), "r"(a[2]), "r"(a[3]), "r"(b[0]), "r"(b[1]));
}
__device__ __forceinline__ float fsig(float x)  { return 1.f / (1.f + __expf(-x)); }
__device__ __forceinline__ float ftanh(float x) { return 2.f / (1.f + __expf(-2.f * x)) - 1.f; }

// ---------- init / prep ----------
__global__ void zero_state_kernel() {
    int idx = blockIdx.x * blockDim.x + threadIdx.x;
    if (idx < BATCH * HH) {
        g_c1[idx] = 0.f; g_c2[idx] = 0.f;
        bf16 z = __float2bfloat16(0.f);
        g_h1_hi[0][idx] = z; g_h1_lo[0][idx] = z;
        g_h2_hi[0][idx] = z; g_h2_lo[0][idx] = z;
    }
}

__global__ void prep_kernel(const float* __restrict__ Wih1, const float* __restrict__ Whh1,
                            const float* __restrict__ bih1, const float* __restrict__ bhh1,
                            const float* __restrict__ Wih2, const float* __restrict__ Whh2,
                            const float* __restrict__ bih2, const float* __restrict__ bhh2) {
    int idx = blockIdx.x * blockDim.x + threadIdx.x;
    if (idx < NG * KK) {
        int r = idx >> 9, k = idx & 511;
        float w1 = (k < 256) ? Wih1[r * 256 + k] : Whh1[r * 256 + (k - 256)];
        bf16 h1 = __float2bfloat16(w1);
        g_W1_hi[idx] = h1;
        g_W1_lo[idx] = __float2bfloat16(w1 - __bfloat162float(h1));
        float w2 = (k < 256) ? Wih2[r * 256 + k] : Whh2[r * 256 + (k - 256)];
        bf16 h2 = __float2bfloat16(w2);
        g_W2_hi[idx] = h2;
        g_W2_lo[idx] = __float2bfloat16(w2 - __bfloat162float(h2));
    }
    if (idx < NG) {
        g_bias1[idx] = bih1[idx] + bhh1[idx];
        g_bias2[idx] = bih2[idx] + bhh2[idx];
    }
}

// ---------- encode ----------
__global__ void encode_kernel(const float* __restrict__ x, const float* __restrict__ W,
                              const float* __restrict__ b) {
    __shared__ float Ws[FF][HH];
    __shared__ float xs[32][FF];
    int tid = threadIdx.x;
    for (int idx = tid; idx < HH * FF; idx += 256) {
        int e = idx / FF, f = idx % FF;
        Ws[f][e] = W[idx];
    }
    long r0 = (long)blockIdx.x * 32;
    for (int idx = tid; idx < 32 * FF; idx += 256) {
        int r = idx / FF, f = idx % FF;
        xs[r][f] = x[(r0 + r) * FF + f];
    }
    __syncthreads();
    float be = b[tid];
    float acc[32];
    #pragma unroll
    for (int r = 0; r < 32; ++r) acc[r] = be;
    #pragma unroll
    for (int f = 0; f < FF; ++f) {
        float w = Ws[f][tid];
        #pragma unroll
        for (int r = 0; r < 32; ++r) acc[r] += xs[r][f] * w;
    }
    #pragma unroll
    for (int r = 0; r < 32; ++r) {
        long o = (r0 + r) * HH + tid;
        bf16 hi = __float2bfloat16(acc[r]);
        g_enc_hi[o] = hi;
        g_enc_lo[o] = __float2bfloat16(acc[r] - __bfloat162float(hi));
    }
}

// ---------- fused LSTM cell (HMMA, 512 threads, 3-stage pipeline) ----------
__device__ __forceinline__ void cell_load(char* stg, int ch, int tid, int m0, int u0,
                                          const bf16* __restrict__ Xhi, const bf16* __restrict__ Xlo,
                                          long xStride,
                                          const bf16* __restrict__ Hhi, const bf16* __restrict__ Hlo,
                                          const bf16* __restrict__ Whi, const bf16* __restrict__ Wlo) {
    const int r  = tid >> 2;             // smem row 0..127
    const int g0 = (tid & 3) << 1;       // first of two 16B granules
    const bf16 *Ah, *Al;
    if (ch < 4) { long o = (long)(m0 + r) * xStride + ch * 64; Ah = Xhi + o; Al = Xlo + o; }
    else        { long o = (long)(m0 + r) * HH + (ch - 4) * 64; Ah = Hhi + o; Al = Hlo + o; }
    const long wrow = (long)(((r >> 5) << 8) + u0 + (r & 31)) * KK + ch * 64;
    const bf16* Bh = Whi + wrow;
    const bf16* Bl = Wlo + wrow;
    char* row = stg + r * (PITCH * 2);
    #pragma unroll
    for (int j = 0; j < 2; ++j) {
        int g = g0 + j;
        int d = g << 4;
        cp16(row + d,               Ah + (g << 3));
        cp16(row + TILE_BB + d,     Al + (g << 3));
        cp16(row + 2 * TILE_BB + d, Bh + (g << 3));
        cp16(row + 3 * TILE_BB + d, Bl + (g << 3));
    }
}

__device__ __forceinline__ void cell_compute(const bf16* sb, int wm, int wn, int lane,
                                             float acc[2][4][4]) {
    const bf16* sAhi = sb;
    const bf16* sAlo = sb + TILE_E;
    const bf16* sBhi = sb + 2 * TILE_E;
    const bf16* sBlo = sb + 3 * TILE_E;
    #pragma unroll
    for (int ks = 0; ks < 4; ++ks) {
        uint32_t ah[2][4], al[2][4], bh[4][2], bl[4][2];
        #pragma unroll
        for (int mt = 0; mt < 2; ++mt) {
            int row = wm * 32 + mt * 16 + (lane & 15);
            int col = ks * 16 + ((lane >> 4) << 3);
            int o = row * PITCH + col;
            ldsm4(ah[mt][0], ah[mt][1], ah[mt][2], ah[mt][3], sAhi + o);
            ldsm4(al[mt][0], al[mt][1], al[mt][2], al[mt][3], sAlo + o);
        }
        #pragma unroll
        for (int np = 0; np < 2; ++np) {
            int row = wn * 32 + np * 16 + ((lane >> 4) << 3) + (lane & 7);
            int col = ks * 16 + (((lane >> 3) & 1) << 3);
            int o = row * PITCH + col;
            ldsm4(bh[2 * np][0], bh[2 * np][1], bh[2 * np + 1][0], bh[2 * np + 1][1], sBhi + o);
            ldsm4(bl[2 * np][0], bl[2 * np][1], bl[2 * np + 1][0], bl[2 * np + 1][1], sBlo + o);
        }
        #pragma unroll
        for (int mt = 0; mt < 2; ++mt)
            #pragma unroll
            for (int nt = 0; nt < 4; ++nt) {
                mma16816(acc[mt][nt], ah[mt], bh[nt]);
                mma16816(acc[mt][nt], ah[mt], bl[nt]);
                mma16816(acc[mt][nt], al[mt], bh[nt]);
            }
    }
}

__global__ void __launch_bounds__(512, 1)
cell_kernel(int layer, int xKind, int xIdx, int hIdx, int outIdx, int slot) {
    extern __shared__ __align__(128) char smem_raw[];
    const int tid  = threadIdx.x;
    const int wid  = tid >> 5;
    const int lane = tid & 31;
    const int wm   = wid & 3;
    const int wn   = wid >> 2;
    const int m0   = blockIdx.x * 128;
    const int u0   = blockIdx.y * 32;

    const bf16 *Whi, *Wlo, *Hhi, *Hlo;
    bf16 *HoHi, *HoLo;
    const float* bias;
    float* cSt;
    if (layer == 1) {
        Whi = g_W1_hi; Wlo = g_W1_lo; bias = g_bias1; cSt = g_c1;
        Hhi = g_h1_hi[hIdx]; Hlo = g_h1_lo[hIdx];
        HoHi = g_h1_hi[outIdx]; HoLo = g_h1_lo[outIdx];
    } else {
        Whi = g_W2_hi; Wlo = g_W2_lo; bias = g_bias2; cSt = g_c2;
        Hhi = g_h2_hi[hIdx]; Hlo = g_h2_lo[hIdx];
        HoHi = g_h2_hi[outIdx]; HoLo = g_h2_lo[outIdx];
    }
    const bf16 *Xhi, *Xlo;
    long xStride;
    if (xKind == 0)      { Xhi = g_enc_hi + (long)xIdx * HH; Xlo = g_enc_lo + (long)xIdx * HH; xStride = TT * HH; }
    else if (xKind == 1) { Xhi = g_h1_hi[xIdx]; Xlo = g_h1_lo[xIdx]; xStride = HH; }
    else                 { Xhi = g_h2_hi[xIdx]; Xlo = g_h2_lo[xIdx]; xStride = HH; }

    float acc[2][4][4];
    #pragma unroll
    for (int a = 0; a < 2; ++a)
        #pragma unroll
        for (int b = 0; b < 4; ++b)
            #pragma unroll
            for (int c = 0; c < 4; ++c) acc[a][b][c] = 0.f;

    // prologue: stages 0, 1
    cell_load(smem_raw + 0 * STAGE_B, 0, tid, m0, u0, Xhi, Xlo, xStride, Hhi, Hlo, Whi, Wlo);
    cp_commit();
    cell_load(smem_raw + 1 * STAGE_B, 1, tid, m0, u0, Xhi, Xlo, xStride, Hhi, Hlo, Whi, Wlo);
    cp_commit();

    #pragma unroll 1
    for (int ch = 0; ch < 8; ++ch) {
        __syncthreads();   // all warps done computing chunk ch-1 (whose buffer we overwrite)
        if (ch + 2 < 8)
            cell_load(smem_raw + ((ch + 2) % 3) * STAGE_B, ch + 2, tid, m0, u0,
                      Xhi, Xlo, xStride, Hhi, Hlo, Whi, Wlo);
        cp_commit();       // possibly empty group — keeps wait bookkeeping uniform
        cp_wait2();        // chunk ch complete
        __syncthreads();
        cell_compute((const bf16*)(smem_raw + (ch % 3) * STAGE_B), wm, wn, lane, acc);
    }
    __syncthreads();

    // epilogue: accumulators -> smem -> LSTM nonlinearity
    float* sAcc = (float*)smem_raw;
    const int PA = 132;
    #pragma unroll
    for (int mt = 0; mt < 2; ++mt)
        #pragma unroll
        for (int nt = 0; nt < 4; ++nt) {
            int row = wm * 32 + mt * 16 + (lane >> 2);
            int col = wn * 32 + nt * 8 + ((lane & 3) << 1);
            *(float2*)&sAcc[row * PA + col]       = make_float2(acc[mt][nt][0], acc[mt][nt][1]);
            *(float2*)&sAcc[(row + 8) * PA + col] = make_float2(acc[mt][nt][2], acc[mt][nt][3]);
        }
    __syncthreads();

    for (int idx = tid; idx < 128 * 32; idx += 512) {
        int row = idx >> 5, u = idx & 31;
        float iv = sAcc[row * PA + u]      + bias[u0 + u];
        float fv = sAcc[row * PA + 32 + u] + bias[256 + u0 + u];
        float gv = sAcc[row * PA + 64 + u] + bias[512 + u0 + u];
        float ov = sAcc[row * PA + 96 + u] + bias[768 + u0 + u];
        long gi = (long)(m0 + row) * HH + u0 + u;
        float c = fsig(fv) * cSt[gi] + fsig(iv) * ftanh(gv);
        cSt[gi] = c;
        float h = fsig(ov) * ftanh(c);
        bf16 hh = __float2bfloat16(h);
        HoHi[gi] = hh;
        HoLo[gi] = __float2bfloat16(h - __bfloat162float(hh));
        if (slot >= 0)
            g_pred[((long)(m0 + row) * TT + slot) * HH + u0 + u] = h;
    }
}

// ---------- decode + cumsum + residual ----------
__global__ void dec_kernel(const float* __restrict__ x, const float* __restrict__ Wdec,
                           const float* __restrict__ bdec, float* __restrict__ out) {
    extern __shared__ float sm[];
    float* sP = sm;              // [64][260]
    float* sW = sm + 64 * 260;   // [34][260]
    int tid = threadIdx.x;
    long b0 = (long)blockIdx.x * 64;

    for (int i = tid; i < 34 * 64; i += 288) {
        int f = i / 64, k4 = i % 64;
        reinterpret_cast<float4*>(sW + f * 260)[k4] =
            reinterpret_cast<const float4*>(Wdec + f * 256)[k4];
    }

    int a = tid;
    bool act = a < 272;
    int rg = a & 15, fp = a >> 4;
    int f0 = fp * 2;
    float acc[4][2];
    float bd0 = 0.f, bd1 = 0.f;
    if (act) {
        bd0 = bdec[f0]; bd1 = bdec[f0 + 1];
        #pragma unroll
        for (int i = 0; i < 4; ++i) {
            long b = b0 + rg * 4 + i;
            acc[i][0] = x[b * (TT * FF) + 9 * FF + f0];
            acc[i][1] = x[b * (TT * FF) + 9 * FF + f0 + 1];
        }
    }

    #pragma unroll 1
    for (int j = 0; j < TT; ++j) {
        __syncthreads();
        for (int i = tid; i < 64 * 64; i += 288) {
            int r = i >> 6, k4 = i & 63;
            reinterpret_cast<float4*>(sP + r * 260)[k4] =
                reinterpret_cast<const float4*>(g_pred + (b0 + r) * (TT * HH) + j * HH)[k4];
        }
        __syncthreads();
        if (act) {
            float s[4][2] = {{0.f, 0.f}, {0.f, 0.f}, {0.f, 0.f}, {0.f, 0.f}};
            #pragma unroll 4
            for (int k = 0; k < 256; k += 4) {
                float4 w0 = *reinterpret_cast<float4*>(sW + f0 * 260 + k);
                float4 w1 = *reinterpret_cast<float4*>(sW + (f0 + 1) * 260 + k);
                #pragma unroll
                for (int i = 0; i < 4; ++i) {
                    float4 p = *reinterpret_cast<float4*>(sP + (rg * 4 + i) * 260 + k);
                    s[i][0] += p.x * w0.x + p.y * w0.y + p.z * w0.z + p.w * w0.w;
                    s[i][1] += p.x * w1.x + p.y * w1.y + p.z * w1.z + p.w * w1.w;
                }
            }
            #pragma unroll
            for (int i = 0; i < 4; ++i) {
                acc[i][0] += s[i][0] + bd0;
                acc[i][1] += s[i][1] + bd1;
                long b = b0 + rg * 4 + i;
                out[b * (TT * FF) + j * FF + f0]     = acc[i][0];
                out[b * (TT * FF) + j * FF + f0 + 1] = acc[i][1];
            }
        }
    }
}

// ---------- launch ----------
extern "C" void kernel_launch(void* const* d_in, const int* in_sizes, int n_in,
                              void* d_out, int out_size) {
    const float* x     = (const float*)d_in[0];
    const float* W_enc = (const float*)d_in[1];
    const float* b_enc = (const float*)d_in[2];
    const float* Wih1  = (const float*)d_in[3];
    const float* Whh1  = (const float*)d_in[4];
    const float* bih1  = (const float*)d_in[5];
    const float* bhh1  = (const float*)d_in[6];
    const float* Wih2  = (const float*)d_in[7];
    const float* Whh2  = (const float*)d_in[8];
    const float* bih2  = (const float*)d_in[9];
    const float* bhh2  = (const float*)d_in[10];
    const float* Wdec  = (const float*)d_in[11];
    const float* bdec  = (const float*)d_in[12];
    float* out = (float*)d_out;

    cudaFuncSetAttribute(cell_kernel, cudaFuncAttributeMaxDynamicSharedMemorySize, SMEM_CELL);
    cudaFuncSetAttribute(dec_kernel,  cudaFuncAttributeMaxDynamicSharedMemorySize, SMEM_DEC);

    zero_state_kernel<<<(BATCH * HH + 255) / 256, 256>>>();
    prep_kernel<<<(NG * KK + 255) / 256, 256>>>(Wih1, Whh1, bih1, bhh1, Wih2, Whh2, bih2, bhh2);
    encode_kernel<<<(BATCH * TT) / 32, 256>>>(x, W_enc, b_enc);

    dim3 cg(BATCH / 128, HH / 32);
    int p1 = 0, p2 = 0;
    for (int t = 0; t < TT; ++t) {
        cell_kernel<<<cg, 512, SMEM_CELL>>>(1, 0, t, p1, p1 ^ 1, -1);
        p1 ^= 1;
        cell_kernel<<<cg, 512, SMEM_CELL>>>(2, 1, p1, p2, p2 ^ 1, (t == 9) ? 0 : -1);
        p2 ^= 1;
    }
    for (int s = 1; s <= 9; ++s) {
        cell_kernel<<<cg, 512, SMEM_CELL>>>(1, 2, p2, p1, p1 ^ 1, -1);
        p1 ^= 1;
        cell_kernel<<<cg, 512, SMEM_CELL>>>(2, 1, p1, p2, p2 ^ 1, s);
        p2 ^= 1;
    }
    dec_kernel<<<BATCH / 64, 288, SMEM_DEC>>>(x, Wdec, bdec, out);
}

// round 11
// speedup vs baseline: 1.1926x; 1.0280x over previous
#include <cuda_runtime.h>
#include <cuda_bf16.h>
#include <cstdint>

typedef __nv_bfloat16 bf16;

#define BATCH 16384
#define TT    10
#define FF    34
#define HH    256
#define NG    1024
#define KK    512

// cell GEMM tiling: CTA tile 128M x 128N, K-chunks of 64, 3 smem stages
#define PITCH   72                        // bf16 elems per smem row (64 data + 8 pad)
#define TILE_E  (128 * PITCH)             // elems per 128x64 tile
#define TILE_BB (TILE_E * 2)              // bytes per tile = 18432
#define STAGE_B (4 * TILE_BB)             // Ahi, Alo, Bhi, Blo = 73728
#define SMEM_CELL (3 * STAGE_B)           // 221184
#define SMEM_DEC  ((64 * 260 + 34 * 260) * 4)  // 101920

// ---------- scratch (device globals; allocation is forbidden) ----------
__device__ bf16  g_enc_hi[BATCH * TT * HH];
__device__ bf16  g_enc_lo[BATCH * TT * HH];
__device__ bf16  g_h1_hi[2][BATCH * HH];
__device__ bf16  g_h1_lo[2][BATCH * HH];
__device__ bf16  g_h2_hi[2][BATCH * HH];
__device__ bf16  g_h2_lo[2][BATCH * HH];
__device__ float g_c1[BATCH * HH];
__device__ float g_c2[BATCH * HH];
__device__ float g_pred[BATCH * TT * HH];
__device__ bf16  g_W1_hi[NG * KK];
__device__ bf16  g_W1_lo[NG * KK];
__device__ bf16  g_W2_hi[NG * KK];
__device__ bf16  g_W2_lo[NG * KK];
__device__ float g_bias1[NG];
__device__ float g_bias2[NG];

// ---------- helpers ----------
__device__ __forceinline__ void cp16(void* sptr, const void* gptr) {
    uint32_t s = (uint32_t)__cvta_generic_to_shared(sptr);
    asm volatile("cp.async.cg.shared.global [%0], [%1], 16;\n" :: "r"(s), "l"(gptr));
}
__device__ __forceinline__ void cp_commit() { asm volatile("cp.async.commit_group;\n" ::); }
__device__ __forceinline__ void cp_wait1()  { asm volatile("cp.async.wait_group 1;\n" ::); }
__device__ __forceinline__ void cp_wait0()  { asm volatile("cp.async.wait_group 0;\n" ::); }

__device__ __forceinline__ void ldsm4(uint32_t& r0, uint32_t& r1, uint32_t& r2, uint32_t& r3,
                                      const void* p) {
    uint32_t a = (uint32_t)__cvta_generic_to_shared(p);
    asm volatile("ldmatrix.sync.aligned.m8n8.x4.shared.b16 {%0,%1,%2,%3}, [%4];\n"
                 : "=r"(r0), "=r"(r1), "=r"(r2), "=r"(r3) : "r"(a));
}
__device__ __forceinline__ void mma16816(float* d, const uint32_t* a, const uint32_t* b) {
    asm volatile("mma.sync.aligned.m16n8k16.row.col.f32.bf16.bf16.f32 "
                 "{%0,%1,%2,%3}, {%4,%5,%6,%7}, {%8,%9}, {%0,%1,%2,%3};\n"
                 : "+f"(d[0]), "+f"(d[1]), "+f"(d[2]), "+f"(d[3])
                 : "r"(a[0]), "r"(a[1]), "r"(a[2]), "r"(a[3]), "r"(b[0]), "r"(b[1]));
}
__device__ __forceinline__ float fsig(float x)  { return 1.f / (1.f + __expf(-x)); }
__device__ __forceinline__ float ftanh(float x) { return 2.f / (1.f + __expf(-2.f * x)) - 1.f; }

// ---------- init / prep ----------
__global__ void zero_state_kernel() {
    int idx = blockIdx.x * blockDim.x + threadIdx.x;
    if (idx < BATCH * HH) {
        g_c1[idx] = 0.f; g_c2[idx] = 0.f;
        bf16 z = __float2bfloat16(0.f);
        g_h1_hi[0][idx] = z; g_h1_lo[0][idx] = z;
        g_h2_hi[0][idx] = z; g_h2_lo[0][idx] = z;
    }
}

__global__ void prep_kernel(const float* __restrict__ Wih1, const float* __restrict__ Whh1,
                            const float* __restrict__ bih1, const float* __restrict__ bhh1,
                            const float* __restrict__ Wih2, const float* __restrict__ Whh2,
                            const float* __restrict__ bih2, const float* __restrict__ bhh2) {
    int idx = blockIdx.x * blockDim.x + threadIdx.x;
    if (idx < NG * KK) {
        int r = idx >> 9, k = idx & 511;
        float w1 = (k < 256) ? Wih1[r * 256 + k] : Whh1[r * 256 + (k - 256)];
        bf16 h1 = __float2bfloat16(w1);
        g_W1_hi[idx] = h1;
        g_W1_lo[idx] = __float2bfloat16(w1 - __bfloat162float(h1));
        float w2 = (k < 256) ? Wih2[r * 256 + k] : Whh2[r * 256 + (k - 256)];
        bf16 h2 = __float2bfloat16(w2);
        g_W2_hi[idx] = h2;
        g_W2_lo[idx] = __float2bfloat16(w2 - __bfloat162float(h2));
    }
    if (idx < NG) {
        g_bias1[idx] = bih1[idx] + bhh1[idx];
        g_bias2[idx] = bih2[idx] + bhh2[idx];
    }
}

// ---------- encode ----------
__global__ void encode_kernel(const float* __restrict__ x, const float* __restrict__ W,
                              const float* __restrict__ b) {
    __shared__ float Ws[FF][HH];
    __shared__ float xs[32][FF];
    int tid = threadIdx.x;
    for (int idx = tid; idx < HH * FF; idx += 256) {
        int e = idx / FF, f = idx % FF;
        Ws[f][e] = W[idx];
    }
    long r0 = (long)blockIdx.x * 32;
    for (int idx = tid; idx < 32 * FF; idx += 256) {
        int r = idx / FF, f = idx % FF;
        xs[r][f] = x[(r0 + r) * FF + f];
    }
    __syncthreads();
    float be = b[tid];
    float acc[32];
    #pragma unroll
    for (int r = 0; r < 32; ++r) acc[r] = be;
    #pragma unroll
    for (int f = 0; f < FF; ++f) {
        float w = Ws[f][tid];
        #pragma unroll
        for (int r = 0; r < 32; ++r) acc[r] += xs[r][f] * w;
    }
    #pragma unroll
    for (int r = 0; r < 32; ++r) {
        long o = (r0 + r) * HH + tid;
        bf16 hi = __float2bfloat16(acc[r]);
        g_enc_hi[o] = hi;
        g_enc_lo[o] = __float2bfloat16(acc[r] - __bfloat162float(hi));
    }
}

// ---------- fused LSTM cell (HMMA, 512 threads, 3-stage, 1 sync/chunk) ----------
__device__ __forceinline__ void cell_load(char* stg, int ch, int tid, int m0, int u0,
                                          const bf16* __restrict__ Xhi, const bf16* __restrict__ Xlo,
                                          long xStride,
                                          const bf16* __restrict__ Hhi, const bf16* __restrict__ Hlo,
                                          const bf16* __restrict__ Whi, const bf16* __restrict__ Wlo) {
    const int r  = tid >> 2;             // smem row 0..127
    const int g0 = (tid & 3) << 1;       // first of two 16B granules
    const bf16 *Ah, *Al;
    if (ch < 4) { long o = (long)(m0 + r) * xStride + ch * 64; Ah = Xhi + o; Al = Xlo + o; }
    else        { long o = (long)(m0 + r) * HH + (ch - 4) * 64; Ah = Hhi + o; Al = Hlo + o; }
    const long wrow = (long)(((r >> 5) << 8) + u0 + (r & 31)) * KK + ch * 64;
    const bf16* Bh = Whi + wrow;
    const bf16* Bl = Wlo + wrow;
    char* row = stg + r * (PITCH * 2);
    #pragma unroll
    for (int j = 0; j < 2; ++j) {
        int g = g0 + j;
        int d = g << 4;
        cp16(row + d,               Ah + (g << 3));
        cp16(row + TILE_BB + d,     Al + (g << 3));
        cp16(row + 2 * TILE_BB + d, Bh + (g << 3));
        cp16(row + 3 * TILE_BB + d, Bl + (g << 3));
    }
}

__device__ __forceinline__ void cell_compute(const bf16* sb, int wm, int wn, int lane,
                                             float acc[2][4][4]) {
    const bf16* sAhi = sb;
    const bf16* sAlo = sb + TILE_E;
    const bf16* sBhi = sb + 2 * TILE_E;
    const bf16* sBlo = sb + 3 * TILE_E;
    #pragma unroll
    for (int ks = 0; ks < 4; ++ks) {
        uint32_t ah[2][4], al[2][4], bh[4][2], bl[4][2];
        #pragma unroll
        for (int mt = 0; mt < 2; ++mt) {
            int row = wm * 32 + mt * 16 + (lane & 15);
            int col = ks * 16 + ((lane >> 4) << 3);
            int o = row * PITCH + col;
            ldsm4(ah[mt][0], ah[mt][1], ah[mt][2], ah[mt][3], sAhi + o);
            ldsm4(al[mt][0], al[mt][1], al[mt][2], al[mt][3], sAlo + o);
        }
        #pragma unroll
        for (int np = 0; np < 2; ++np) {
            int row = wn * 32 + np * 16 + ((lane >> 4) << 3) + (lane & 7);
            int col = ks * 16 + (((lane >> 3) & 1) << 3);
            int o = row * PITCH + col;
            ldsm4(bh[2 * np][0], bh[2 * np][1], bh[2 * np + 1][0], bh[2 * np + 1][1], sBhi + o);
            ldsm4(bl[2 * np][0], bl[2 * np][1], bl[2 * np + 1][0], bl[2 * np + 1][1], sBlo + o);
        }
        // grouped by product: per-acc order stays hh, hl, lh (bitwise identical),
        // but dependent MMAs into the same accumulator are now 8 issues apart.
        #pragma unroll
        for (int mt = 0; mt < 2; ++mt)
            #pragma unroll
            for (int nt = 0; nt < 4; ++nt)
                mma16816(acc[mt][nt], ah[mt], bh[nt]);
        #pragma unroll
        for (int mt = 0; mt < 2; ++mt)
            #pragma unroll
            for (int nt = 0; nt < 4; ++nt)
                mma16816(acc[mt][nt], ah[mt], bl[nt]);
        #pragma unroll
        for (int mt = 0; mt < 2; ++mt)
            #pragma unroll
            for (int nt = 0; nt < 4; ++nt)
                mma16816(acc[mt][nt], al[mt], bh[nt]);
    }
}

__global__ void __launch_bounds__(512, 1)
cell_kernel(int layer, int xKind, int xIdx, int hIdx, int outIdx, int slot) {
    extern __shared__ __align__(128) char smem_raw[];
    const int tid  = threadIdx.x;
    const int wid  = tid >> 5;
    const int lane = tid & 31;
    const int wm   = wid & 3;
    const int wn   = wid >> 2;
    const int m0   = blockIdx.x * 128;
    const int u0   = blockIdx.y * 32;

    const bf16 *Whi, *Wlo, *Hhi, *Hlo;
    bf16 *HoHi, *HoLo;
    const float* bias;
    float* cSt;
    if (layer == 1) {
        Whi = g_W1_hi; Wlo = g_W1_lo; bias = g_bias1; cSt = g_c1;
        Hhi = g_h1_hi[hIdx]; Hlo = g_h1_lo[hIdx];
        HoHi = g_h1_hi[outIdx]; HoLo = g_h1_lo[outIdx];
    } else {
        Whi = g_W2_hi; Wlo = g_W2_lo; bias = g_bias2; cSt = g_c2;
        Hhi = g_h2_hi[hIdx]; Hlo = g_h2_lo[hIdx];
        HoHi = g_h2_hi[outIdx]; HoLo = g_h2_lo[outIdx];
    }
    const bf16 *Xhi, *Xlo;
    long xStride;
    if (xKind == 0)      { Xhi = g_enc_hi + (long)xIdx * HH; Xlo = g_enc_lo + (long)xIdx * HH; xStride = TT * HH; }
    else if (xKind == 1) { Xhi = g_h1_hi[xIdx]; Xlo = g_h1_lo[xIdx]; xStride = HH; }
    else                 { Xhi = g_h2_hi[xIdx]; Xlo = g_h2_lo[xIdx]; xStride = HH; }

    float acc[2][4][4];
    #pragma unroll
    for (int a = 0; a < 2; ++a)
        #pragma unroll
        for (int b = 0; b < 4; ++b)
            #pragma unroll
            for (int c = 0; c < 4; ++c) acc[a][b][c] = 0.f;

    // prologue: stages 0, 1 in flight
    cell_load(smem_raw + 0 * STAGE_B, 0, tid, m0, u0, Xhi, Xlo, xStride, Hhi, Hlo, Whi, Wlo);
    cp_commit();
    cell_load(smem_raw + 1 * STAGE_B, 1, tid, m0, u0, Xhi, Xlo, xStride, Hhi, Hlo, Whi, Wlo);
    cp_commit();

    // mainloop: ONE barrier per chunk.
    //   wait(ch arrived) -> sync (publishes ch to all AND releases slot of ch-1)
    //   -> load ch+2 into slot (ch+2)%3 == slot (ch-1)%3 -> compute ch
    #pragma unroll 1
    for (int ch = 0; ch < 8; ++ch) {
        if (ch < 7) cp_wait1(); else cp_wait0();
        __syncthreads();
        if (ch + 2 < 8) {
            cell_load(smem_raw + ((ch + 2) % 3) * STAGE_B, ch + 2, tid, m0, u0,
                      Xhi, Xlo, xStride, Hhi, Hlo, Whi, Wlo);
            cp_commit();
        }
        cell_compute((const bf16*)(smem_raw + (ch % 3) * STAGE_B), wm, wn, lane, acc);
    }
    __syncthreads();

    // epilogue: accumulators -> smem -> LSTM nonlinearity
    float* sAcc = (float*)smem_raw;
    const int PA = 132;
    #pragma unroll
    for (int mt = 0; mt < 2; ++mt)
        #pragma unroll
        for (int nt = 0; nt < 4; ++nt) {
            int row = wm * 32 + mt * 16 + (lane >> 2);
            int col = wn * 32 + nt * 8 + ((lane & 3) << 1);
            *(float2*)&sAcc[row * PA + col]       = make_float2(acc[mt][nt][0], acc[mt][nt][1]);
            *(float2*)&sAcc[(row + 8) * PA + col] = make_float2(acc[mt][nt][2], acc[mt][nt][3]);
        }
    __syncthreads();

    for (int idx = tid; idx < 128 * 32; idx += 512) {
        int row = idx >> 5, u = idx & 31;
        float iv = sAcc[row * PA + u]      + bias[u0 + u];
        float fv = sAcc[row * PA + 32 + u] + bias[256 + u0 + u];
        float gv = sAcc[row * PA + 64 + u] + bias[512 + u0 + u];
        float ov = sAcc[row * PA + 96 + u] + bias[768 + u0 + u];
        long gi = (long)(m0 + row) * HH + u0 + u;
        float c = fsig(fv) * cSt[gi] + fsig(iv) * ftanh(gv);
        cSt[gi] = c;
        float h = fsig(ov) * ftanh(c);
        bf16 hh = __float2bfloat16(h);
        HoHi[gi] = hh;
        HoLo[gi] = __float2bfloat16(h - __bfloat162float(hh));
        if (slot >= 0)
            g_pred[((long)(m0 + row) * TT + slot) * HH + u0 + u] = h;
    }
}

// ---------- decode + cumsum + residual ----------
__global__ void dec_kernel(const float* __restrict__ x, const float* __restrict__ Wdec,
                           const float* __restrict__ bdec, float* __restrict__ out) {
    extern __shared__ float sm[];
    float* sP = sm;              // [64][260]
    float* sW = sm + 64 * 260;   // [34][260]
    int tid = threadIdx.x;
    long b0 = (long)blockIdx.x * 64;

    for (int i = tid; i < 34 * 64; i += 288) {
        int f = i / 64, k4 = i % 64;
        reinterpret_cast<float4*>(sW + f * 260)[k4] =
            reinterpret_cast<const float4*>(Wdec + f * 256)[k4];
    }

    int a = tid;
    bool act = a < 272;
    int rg = a & 15, fp = a >> 4;
    int f0 = fp * 2;
    float acc[4][2];
    float bd0 = 0.f, bd1 = 0.f;
    if (act) {
        bd0 = bdec[f0]; bd1 = bdec[f0 + 1];
        #pragma unroll
        for (int i = 0; i < 4; ++i) {
            long b = b0 + rg * 4 + i;
            acc[i][0] = x[b * (TT * FF) + 9 * FF + f0];
            acc[i][1] = x[b * (TT * FF) + 9 * FF + f0 + 1];
        }
    }

    #pragma unroll 1
    for (int j = 0; j < TT; ++j) {
        __syncthreads();
        for (int i = tid; i < 64 * 64; i += 288) {
            int r = i >> 6, k4 = i & 63;
            reinterpret_cast<float4*>(sP + r * 260)[k4] =
                reinterpret_cast<const float4*>(g_pred + (b0 + r) * (TT * HH) + j * HH)[k4];
        }
        __syncthreads();
        if (act) {
            float s[4][2] = {{0.f, 0.f}, {0.f, 0.f}, {0.f, 0.f}, {0.f, 0.f}};
            #pragma unroll 4
            for (int k = 0; k < 256; k += 4) {
                float4 w0 = *reinterpret_cast<float4*>(sW + f0 * 260 + k);
                float4 w1 = *reinterpret_cast<float4*>(sW + (f0 + 1) * 260 + k);
                #pragma unroll
                for (int i = 0; i < 4; ++i) {
                    float4 p = *reinterpret_cast<float4*>(sP + (rg * 4 + i) * 260 + k);
                    s[i][0] += p.x * w0.x + p.y * w0.y + p.z * w0.z + p.w * w0.w;
                    s[i][1] += p.x * w1.x + p.y * w1.y + p.z * w1.z + p.w * w1.w;
                }
            }
            #pragma unroll
            for (int i = 0; i < 4; ++i) {
                acc[i][0] += s[i][0] + bd0;
                acc[i][1] += s[i][1] + bd1;
                long b = b0 + rg * 4 + i;
                out[b * (TT * FF) + j * FF + f0]     = acc[i][0];
                out[b * (TT * FF) + j * FF + f0 + 1] = acc[i][1];
            }
        }
    }
}

// ---------- launch ----------
extern "C" void kernel_launch(void* const* d_in, const int* in_sizes, int n_in,
                              void* d_out, int out_size) {
    const float* x     = (const float*)d_in[0];
    const float* W_enc = (const float*)d_in[1];
    const float* b_enc = (const float*)d_in[2];
    const float* Wih1  = (const float*)d_in[3];
    const float* Whh1  = (const float*)d_in[4];
    const float* bih1  = (const float*)d_in[5];
    const float* bhh1  = (const float*)d_in[6];
    const float* Wih2  = (const float*)d_in[7];
    const float* Whh2  = (const float*)d_in[8];
    const float* bih2  = (const float*)d_in[9];
    const float* bhh2  = (const float*)d_in[10];
    const float* Wdec  = (const float*)d_in[11];
    const float* bdec  = (const float*)d_in[12];
    float* out = (float*)d_out;

    cudaFuncSetAttribute(cell_kernel, cudaFuncAttributeMaxDynamicSharedMemorySize, SMEM_CELL);
    cudaFuncSetAttribute(dec_kernel,  cudaFuncAttributeMaxDynamicSharedMemorySize, SMEM_DEC);

    zero_state_kernel<<<(BATCH * HH + 255) / 256, 256>>>();
    prep_kernel<<<(NG * KK + 255) / 256, 256>>>(Wih1, Whh1, bih1, bhh1, Wih2, Whh2, bih2, bhh2);
    encode_kernel<<<(BATCH * TT) / 32, 256>>>(x, W_enc, b_enc);

    dim3 cg(BATCH / 128, HH / 32);
    int p1 = 0, p2 = 0;
    for (int t = 0; t < TT; ++t) {
        cell_kernel<<<cg, 512, SMEM_CELL>>>(1, 0, t, p1, p1 ^ 1, -1);
        p1 ^= 1;
        cell_kernel<<<cg, 512, SMEM_CELL>>>(2, 1, p1, p2, p2 ^ 1, (t == 9) ? 0 : -1);
        p2 ^= 1;
    }
    for (int s = 1; s <= 9; ++s) {
        cell_kernel<<<cg, 512, SMEM_CELL>>>(1, 2, p2, p1, p1 ^ 1, -1);
        p1 ^= 1;
        cell_kernel<<<cg, 512, SMEM_CELL>>>(2, 1, p1, p2, p2 ^ 1, s);
        p2 ^= 1;
    }
    dec_kernel<<<BATCH / 64, 288, SMEM_DEC>>>(x, Wdec, bdec, out);
}

// round 14
// speedup vs baseline: 1.5089x; 1.2653x over previous
#include <cuda_runtime.h>
#include <cuda_fp16.h>
#include <cstdint>

typedef __half fp16;

#define BATCH 16384
#define TT    10
#define FF    34
#define HH    256
#define NG    1024
#define KK    512

// cell GEMM tiling: CTA tile 128M x 128N, K-chunks of 64, 3 smem stages
#define PITCH   72                        // fp16 elems per smem row (64 data + 8 pad)
#define TILE_E  (128 * PITCH)             // elems per 128x64 tile
#define TILE_BB (TILE_E * 2)              // bytes per tile = 18432
#define STAGE_B (3 * TILE_BB)             // Ahi, Alo, W = 55296
#define SMEM_CELL (3 * STAGE_B)           // 165888
#define SMEM_DEC  ((64 * 260 + 34 * 260) * 4)  // 101920

// ---------- scratch (device globals; allocation is forbidden) ----------
__device__ fp16  g_enc_hi[BATCH * TT * HH];
__device__ fp16  g_enc_lo[BATCH * TT * HH];
__device__ fp16  g_h1_hi[2][BATCH * HH];
__device__ fp16  g_h1_lo[2][BATCH * HH];
__device__ fp16  g_h2_hi[2][BATCH * HH];
__device__ fp16  g_h2_lo[2][BATCH * HH];
__device__ float g_c1[BATCH * HH];
__device__ float g_c2[BATCH * HH];
__device__ float g_pred[BATCH * TT * HH];
__device__ fp16  g_W1[NG * KK];
__device__ fp16  g_W2[NG * KK];
__device__ float g_bias1[NG];
__device__ float g_bias2[NG];

// ---------- helpers ----------
__device__ __forceinline__ void cp16(void* sptr, const void* gptr) {
    uint32_t s = (uint32_t)__cvta_generic_to_shared(sptr);
    asm volatile("cp.async.cg.shared.global [%0], [%1], 16;\n" :: "r"(s), "l"(gptr));
}
__device__ __forceinline__ void cp_commit() { asm volatile("cp.async.commit_group;\n" ::); }
__device__ __forceinline__ void cp_wait1()  { asm volatile("cp.async.wait_group 1;\n" ::); }
__device__ __forceinline__ void cp_wait0()  { asm volatile("cp.async.wait_group 0;\n" ::); }

__device__ __forceinline__ void ldsm4(uint32_t& r0, uint32_t& r1, uint32_t& r2, uint32_t& r3,
                                      const void* p) {
    uint32_t a = (uint32_t)__cvta_generic_to_shared(p);
    asm volatile("ldmatrix.sync.aligned.m8n8.x4.shared.b16 {%0,%1,%2,%3}, [%4];\n"
                 : "=r"(r0), "=r"(r1), "=r"(r2), "=r"(r3) : "r"(a));
}
__device__ __forceinline__ void mma16816(float* d, const uint32_t* a, const uint32_t* b) {
    asm volatile("mma.sync.aligned.m16n8k16.row.col.f32.f16.f16.f32 "
                 "{%0,%1,%2,%3}, {%4,%5,%6,%7}, {%8,%9}, {%0,%1,%2,%3};\n"
                 : "+f"(d[0]), "+f"(d[1]), "+f"(d[2]), "+f"(d[3])
                 : "r"(a[0]), "r"(a[1]), "r"(a[2]), "r"(a[3]), "r"(b[0]), "r"(b[1]));
}
__device__ __forceinline__ float fsig(float x)  { return 1.f / (1.f + __expf(-x)); }
__device__ __forceinline__ float ftanh(float x) { return 2.f / (1.f + __expf(-2.f * x)) - 1.f; }

// ---------- init / prep ----------
__global__ void zero_state_kernel() {
    int idx = blockIdx.x * blockDim.x + threadIdx.x;
    if (idx < BATCH * HH) {
        g_c1[idx] = 0.f; g_c2[idx] = 0.f;
        fp16 z = __float2half(0.f);
        g_h1_hi[0][idx] = z; g_h1_lo[0][idx] = z;
        g_h2_hi[0][idx] = z; g_h2_lo[0][idx] = z;
    }
}

__global__ void prep_kernel(const float* __restrict__ Wih1, const float* __restrict__ Whh1,
                            const float* __restrict__ bih1, const float* __restrict__ bhh1,
                            const float* __restrict__ Wih2, const float* __restrict__ Whh2,
                            const float* __restrict__ bih2, const float* __restrict__ bhh2) {
    int idx = blockIdx.x * blockDim.x + threadIdx.x;
    if (idx < NG * KK) {
        int r = idx >> 9, k = idx & 511;
        float w1 = (k < 256) ? Wih1[r * 256 + k] : Whh1[r * 256 + (k - 256)];
        g_W1[idx] = __float2half(w1);
        float w2 = (k < 256) ? Wih2[r * 256 + k] : Whh2[r * 256 + (k - 256)];
        g_W2[idx] = __float2half(w2);
    }
    if (idx < NG) {
        g_bias1[idx] = bih1[idx] + bhh1[idx];
        g_bias2[idx] = bih2[idx] + bhh2[idx];
    }
}

// ---------- encode ----------
__global__ void encode_kernel(const float* __restrict__ x, const float* __restrict__ W,
                              const float* __restrict__ b) {
    __shared__ float Ws[FF][HH];
    __shared__ float xs[32][FF];
    int tid = threadIdx.x;
    for (int idx = tid; idx < HH * FF; idx += 256) {
        int e = idx / FF, f = idx % FF;
        Ws[f][e] = W[idx];
    }
    long r0 = (long)blockIdx.x * 32;
    for (int idx = tid; idx < 32 * FF; idx += 256) {
        int r = idx / FF, f = idx % FF;
        xs[r][f] = x[(r0 + r) * FF + f];
    }
    __syncthreads();
    float be = b[tid];
    float acc[32];
    #pragma unroll
    for (int r = 0; r < 32; ++r) acc[r] = be;
    #pragma unroll
    for (int f = 0; f < FF; ++f) {
        float w = Ws[f][tid];
        #pragma unroll
        for (int r = 0; r < 32; ++r) acc[r] += xs[r][f] * w;
    }
    #pragma unroll
    for (int r = 0; r < 32; ++r) {
        long o = (r0 + r) * HH + tid;
        fp16 hi = __float2half(acc[r]);
        g_enc_hi[o] = hi;
        g_enc_lo[o] = __float2half(acc[r] - __half2float(hi));
    }
}

// ---------- fused LSTM cell (fp16 HMMA, 2 products, 512 thr, 3-stage, 1 sync/chunk) ----------
__device__ __forceinline__ void cell_load(char* stg, int ch, int tid, int m0, int u0,
                                          const fp16* __restrict__ Xhi, const fp16* __restrict__ Xlo,
                                          long xStride,
                                          const fp16* __restrict__ Hhi, const fp16* __restrict__ Hlo,
                                          const fp16* __restrict__ W) {
    const int r  = tid >> 2;             // smem row 0..127
    const int g0 = (tid & 3) << 1;       // first of two 16B granules
    const fp16 *Ah, *Al;
    if (ch < 4) { long o = (long)(m0 + r) * xStride + ch * 64; Ah = Xhi + o; Al = Xlo + o; }
    else        { long o = (long)(m0 + r) * HH + (ch - 4) * 64; Ah = Hhi + o; Al = Hlo + o; }
    const fp16* Bw = W + (long)(((r >> 5) << 8) + u0 + (r & 31)) * KK + ch * 64;
    char* row = stg + r * (PITCH * 2);
    #pragma unroll
    for (int j = 0; j < 2; ++j) {
        int g = g0 + j;
        int d = g << 4;
        cp16(row + d,               Ah + (g << 3));
        cp16(row + TILE_BB + d,     Al + (g << 3));
        cp16(row + 2 * TILE_BB + d, Bw + (g << 3));
    }
}

__device__ __forceinline__ void cell_compute(const fp16* sb, int wm, int wn, int lane,
                                             float acc[2][4][4]) {
    const fp16* sAhi = sb;
    const fp16* sAlo = sb + TILE_E;
    const fp16* sBw  = sb + 2 * TILE_E;
    #pragma unroll
    for (int ks = 0; ks < 4; ++ks) {
        uint32_t ah[2][4], al[2][4], bw[4][2];
        #pragma unroll
        for (int mt = 0; mt < 2; ++mt) {
            int row = wm * 32 + mt * 16 + (lane & 15);
            int col = ks * 16 + ((lane >> 4) << 3);
            int o = row * PITCH + col;
            ldsm4(ah[mt][0], ah[mt][1], ah[mt][2], ah[mt][3], sAhi + o);
            ldsm4(al[mt][0], al[mt][1], al[mt][2], al[mt][3], sAlo + o);
        }
        #pragma unroll
        for (int np = 0; np < 2; ++np) {
            int row = wn * 32 + np * 16 + ((lane >> 4) << 3) + (lane & 7);
            int col = ks * 16 + (((lane >> 3) & 1) << 3);
            int o = row * PITCH + col;
            ldsm4(bw[2 * np][0], bw[2 * np][1], bw[2 * np + 1][0], bw[2 * np + 1][1], sBw + o);
        }
        // grouped by product: per-acc order is ah*w then al*w; dependent MMAs
        // into the same accumulator are 8 issues apart.
        #pragma unroll
        for (int mt = 0; mt < 2; ++mt)
            #pragma unroll
            for (int nt = 0; nt < 4; ++nt)
                mma16816(acc[mt][nt], ah[mt], bw[nt]);
        #pragma unroll
        for (int mt = 0; mt < 2; ++mt)
            #pragma unroll
            for (int nt = 0; nt < 4; ++nt)
                mma16816(acc[mt][nt], al[mt], bw[nt]);
    }
}

__global__ void __launch_bounds__(512, 1)
cell_kernel(int layer, int xKind, int xIdx, int hIdx, int outIdx, int slot) {
    extern __shared__ __align__(128) char smem_raw[];
    const int tid  = threadIdx.x;
    const int wid  = tid >> 5;
    const int lane = tid & 31;
    const int wm   = wid & 3;
    const int wn   = wid >> 2;
    const int m0   = blockIdx.x * 128;
    const int u0   = blockIdx.y * 32;

    const fp16 *W, *Hhi, *Hlo;
    fp16 *HoHi, *HoLo;
    const float* bias;
    float* cSt;
    if (layer == 1) {
        W = g_W1; bias = g_bias1; cSt = g_c1;
        Hhi = g_h1_hi[hIdx]; Hlo = g_h1_lo[hIdx];
        HoHi = g_h1_hi[outIdx]; HoLo = g_h1_lo[outIdx];
    } else {
        W = g_W2; bias = g_bias2; cSt = g_c2;
        Hhi = g_h2_hi[hIdx]; Hlo = g_h2_lo[hIdx];
        HoHi = g_h2_hi[outIdx]; HoLo = g_h2_lo[outIdx];
    }
    const fp16 *Xhi, *Xlo;
    long xStride;
    if (xKind == 0)      { Xhi = g_enc_hi + (long)xIdx * HH; Xlo = g_enc_lo + (long)xIdx * HH; xStride = TT * HH; }
    else if (xKind == 1) { Xhi = g_h1_hi[xIdx]; Xlo = g_h1_lo[xIdx]; xStride = HH; }
    else                 { Xhi = g_h2_hi[xIdx]; Xlo = g_h2_lo[xIdx]; xStride = HH; }

    float acc[2][4][4];
    #pragma unroll
    for (int a = 0; a < 2; ++a)
        #pragma unroll
        for (int b = 0; b < 4; ++b)
            #pragma unroll
            for (int c = 0; c < 4; ++c) acc[a][b][c] = 0.f;

    // prologue: stages 0, 1 in flight
    cell_load(smem_raw + 0 * STAGE_B, 0, tid, m0, u0, Xhi, Xlo, xStride, Hhi, Hlo, W);
    cp_commit();
    cell_load(smem_raw + 1 * STAGE_B, 1, tid, m0, u0, Xhi, Xlo, xStride, Hhi, Hlo, W);
    cp_commit();

    // mainloop: ONE barrier per chunk.
    #pragma unroll 1
    for (int ch = 0; ch < 8; ++ch) {
        if (ch < 7) cp_wait1(); else cp_wait0();
        __syncthreads();
        if (ch + 2 < 8) {
            cell_load(smem_raw + ((ch + 2) % 3) * STAGE_B, ch + 2, tid, m0, u0,
                      Xhi, Xlo, xStride, Hhi, Hlo, W);
            cp_commit();
        }
        cell_compute((const fp16*)(smem_raw + (ch % 3) * STAGE_B), wm, wn, lane, acc);
    }
    __syncthreads();

    // epilogue: accumulators -> smem -> LSTM nonlinearity
    float* sAcc = (float*)smem_raw;
    const int PA = 132;
    #pragma unroll
    for (int mt = 0; mt < 2; ++mt)
        #pragma unroll
        for (int nt = 0; nt < 4; ++nt) {
            int row = wm * 32 + mt * 16 + (lane >> 2);
            int col = wn * 32 + nt * 8 + ((lane & 3) << 1);
            *(float2*)&sAcc[row * PA + col]       = make_float2(acc[mt][nt][0], acc[mt][nt][1]);
            *(float2*)&sAcc[(row + 8) * PA + col] = make_float2(acc[mt][nt][2], acc[mt][nt][3]);
        }
    __syncthreads();

    for (int idx = tid; idx < 128 * 32; idx += 512) {
        int row = idx >> 5, u = idx & 31;
        float iv = sAcc[row * PA + u]      + bias[u0 + u];
        float fv = sAcc[row * PA + 32 + u] + bias[256 + u0 + u];
        float gv = sAcc[row * PA + 64 + u] + bias[512 + u0 + u];
        float ov = sAcc[row * PA + 96 + u] + bias[768 + u0 + u];
        long gi = (long)(m0 + row) * HH + u0 + u;
        float c = fsig(fv) * cSt[gi] + fsig(iv) * ftanh(gv);
        cSt[gi] = c;
        float h = fsig(ov) * ftanh(c);
        fp16 hh = __float2half(h);
        HoHi[gi] = hh;
        HoLo[gi] = __float2half(h - __half2float(hh));
        if (slot >= 0)
            g_pred[((long)(m0 + row) * TT + slot) * HH + u0 + u] = h;
    }
}

// ---------- decode + cumsum + residual ----------
__global__ void dec_kernel(const float* __restrict__ x, const float* __restrict__ Wdec,
                           const float* __restrict__ bdec, float* __restrict__ out) {
    extern __shared__ float sm[];
    float* sP = sm;              // [64][260]
    float* sW = sm + 64 * 260;   // [34][260]
    int tid = threadIdx.x;
    long b0 = (long)blockIdx.x * 64;

    for (int i = tid; i < 34 * 64; i += 288) {
        int f = i / 64, k4 = i % 64;
        reinterpret_cast<float4*>(sW + f * 260)[k4] =
            reinterpret_cast<const float4*>(Wdec + f * 256)[k4];
    }

    int a = tid;
    bool act = a < 272;
    int rg = a & 15, fp = a >> 4;
    int f0 = fp * 2;
    float acc[4][2];
    float bd0 = 0.f, bd1 = 0.f;
    if (act) {
        bd0 = bdec[f0]; bd1 = bdec[f0 + 1];
        #pragma unroll
        for (int i = 0; i < 4; ++i) {
            long b = b0 + rg * 4 + i;
            acc[i][0] = x[b * (TT * FF) + 9 * FF + f0];
            acc[i][1] = x[b * (TT * FF) + 9 * FF + f0 + 1];
        }
    }

    #pragma unroll 1
    for (int j = 0; j < TT; ++j) {
        __syncthreads();
        for (int i = tid; i < 64 * 64; i += 288) {
            int r = i >> 6, k4 = i & 63;
            reinterpret_cast<float4*>(sP + r * 260)[k4] =
                reinterpret_cast<const float4*>(g_pred + (b0 + r) * (TT * HH) + j * HH)[k4];
        }
        __syncthreads();
        if (act) {
            float s[4][2] = {{0.f, 0.f}, {0.f, 0.f}, {0.f, 0.f}, {0.f, 0.f}};
            #pragma unroll 4
            for (int k = 0; k < 256; k += 4) {
                float4 w0 = *reinterpret_cast<float4*>(sW + f0 * 260 + k);
                float4 w1 = *reinterpret_cast<float4*>(sW + (f0 + 1) * 260 + k);
                #pragma unroll
                for (int i = 0; i < 4; ++i) {
                    float4 p = *reinterpret_cast<float4*>(sP + (rg * 4 + i) * 260 + k);
                    s[i][0] += p.x * w0.x + p.y * w0.y + p.z * w0.z + p.w * w0.w;
                    s[i][1] += p.x * w1.x + p.y * w1.y + p.z * w1.z + p.w * w1.w;
                }
            }
            #pragma unroll
            for (int i = 0; i < 4; ++i) {
                acc[i][0] += s[i][0] + bd0;
                acc[i][1] += s[i][1] + bd1;
                long b = b0 + rg * 4 + i;
                out[b * (TT * FF) + j * FF + f0]     = acc[i][0];
                out[b * (TT * FF) + j * FF + f0 + 1] = acc[i][1];
            }
        }
    }
}

// ---------- launch ----------
extern "C" void kernel_launch(void* const* d_in, const int* in_sizes, int n_in,
                              void* d_out, int out_size) {
    const float* x     = (const float*)d_in[0];
    const float* W_enc = (const float*)d_in[1];
    const float* b_enc = (const float*)d_in[2];
    const float* Wih1  = (const float*)d_in[3];
    const float* Whh1  = (const float*)d_in[4];
    const float* bih1  = (const float*)d_in[5];
    const float* bhh1  = (const float*)d_in[6];
    const float* Wih2  = (const float*)d_in[7];
    const float* Whh2  = (const float*)d_in[8];
    const float* bih2  = (const float*)d_in[9];
    const float* bhh2  = (const float*)d_in[10];
    const float* Wdec  = (const float*)d_in[11];
    const float* bdec  = (const float*)d_in[12];
    float* out = (float*)d_out;

    cudaFuncSetAttribute(cell_kernel, cudaFuncAttributeMaxDynamicSharedMemorySize, SMEM_CELL);
    cudaFuncSetAttribute(dec_kernel,  cudaFuncAttributeMaxDynamicSharedMemorySize, SMEM_DEC);

    zero_state_kernel<<<(BATCH * HH + 255) / 256, 256>>>();
    prep_kernel<<<(NG * KK + 255) / 256, 256>>>(Wih1, Whh1, bih1, bhh1, Wih2, Whh2, bih2, bhh2);
    encode_kernel<<<(BATCH * TT) / 32, 256>>>(x, W_enc, b_enc);

    dim3 cg(BATCH / 128, HH / 32);
    int p1 = 0, p2 = 0;
    for (int t = 0; t < TT; ++t) {
        cell_kernel<<<cg, 512, SMEM_CELL>>>(1, 0, t, p1, p1 ^ 1, -1);
        p1 ^= 1;
        cell_kernel<<<cg, 512, SMEM_CELL>>>(2, 1, p1, p2, p2 ^ 1, (t == 9) ? 0 : -1);
        p2 ^= 1;
    }
    for (int s = 1; s <= 9; ++s) {
        cell_kernel<<<cg, 512, SMEM_CELL>>>(1, 2, p2, p1, p1 ^ 1, -1);
        p1 ^= 1;
        cell_kernel<<<cg, 512, SMEM_CELL>>>(2, 1, p1, p2, p2 ^ 1, s);
        p2 ^= 1;
    }
    dec_kernel<<<BATCH / 64, 288, SMEM_DEC>>>(x, Wdec, bdec, out);
}

// round 15
// speedup vs baseline: 1.5200x; 1.0073x over previous
#include <cuda_runtime.h>
#include <cuda_fp16.h>
#include <cstdint>

typedef __half fp16;

#define BATCH 16384
#define TT    10
#define FF    34
#define HH    256
#define NG    1024
#define KK    512

// cell GEMM tiling: CTA tile 128M x 128N, K-chunks of 64, 3 smem stages
#define PITCH   72                        // fp16 elems per smem row (64 data + 8 pad)
#define TILE_E  (128 * PITCH)             // elems per 128x64 tile
#define TILE_BB (TILE_E * 2)              // bytes per tile = 18432
#define STAGE_B (3 * TILE_BB)             // Ahi, Alo, W = 55296
#define SMEM_CELL (3 * STAGE_B)           // 165888
#define SMEM_DEC  ((64 * 260 + 34 * 260) * 4)  // 101920

// ---------- scratch (device globals; allocation is forbidden) ----------
__device__ fp16  g_enc_hi[BATCH * TT * HH];
__device__ fp16  g_enc_lo[BATCH * TT * HH];
__device__ fp16  g_h1_hi[2][BATCH * HH];
__device__ fp16  g_h1_lo[2][BATCH * HH];
__device__ fp16  g_h2_hi[2][BATCH * HH];
__device__ fp16  g_h2_lo[2][BATCH * HH];
__device__ float g_c1[BATCH * HH];
__device__ float g_c2[BATCH * HH];
__device__ float g_pred[BATCH * TT * HH];
__device__ fp16  g_W1[NG * KK];
__device__ fp16  g_W2[NG * KK];
__device__ float g_bias1[NG];
__device__ float g_bias2[NG];

// ---------- helpers ----------
__device__ __forceinline__ void cp16(void* sptr, const void* gptr) {
    uint32_t s = (uint32_t)__cvta_generic_to_shared(sptr);
    asm volatile("cp.async.cg.shared.global [%0], [%1], 16;\n" :: "r"(s), "l"(gptr));
}
__device__ __forceinline__ void cp_commit() { asm volatile("cp.async.commit_group;\n" ::); }
__device__ __forceinline__ void cp_wait1()  { asm volatile("cp.async.wait_group 1;\n" ::); }
__device__ __forceinline__ void cp_wait0()  { asm volatile("cp.async.wait_group 0;\n" ::); }

__device__ __forceinline__ void ldsm4(uint32_t& r0, uint32_t& r1, uint32_t& r2, uint32_t& r3,
                                      const void* p) {
    uint32_t a = (uint32_t)__cvta_generic_to_shared(p);
    asm volatile("ldmatrix.sync.aligned.m8n8.x4.shared.b16 {%0,%1,%2,%3}, [%4];\n"
                 : "=r"(r0), "=r"(r1), "=r"(r2), "=r"(r3) : "r"(a));
}
__device__ __forceinline__ void mma16816(float* d, const uint32_t* a, const uint32_t* b) {
    asm volatile("mma.sync.aligned.m16n8k16.row.col.f32.f16.f16.f32 "
                 "{%0,%1,%2,%3}, {%4,%5,%6,%7}, {%8,%9}, {%0,%1,%2,%3};\n"
                 : "+f"(d[0]), "+f"(d[1]), "+f"(d[2]), "+f"(d[3])
                 : "r"(a[0]), "r"(a[1]), "r"(a[2]), "r"(a[3]), "r"(b[0]), "r"(b[1]));
}
__device__ __forceinline__ float fsig(float x)  { return 1.f / (1.f + __expf(-x)); }
__device__ __forceinline__ float ftanh(float x) { return 2.f / (1.f + __expf(-2.f * x)) - 1.f; }

// ---------- init / prep ----------
__global__ void zero_state_kernel() {
    int idx = blockIdx.x * blockDim.x + threadIdx.x;
    if (idx < BATCH * HH) {
        g_c1[idx] = 0.f; g_c2[idx] = 0.f;
        fp16 z = __float2half(0.f);
        g_h1_hi[0][idx] = z; g_h1_lo[0][idx] = z;
        g_h2_hi[0][idx] = z; g_h2_lo[0][idx] = z;
    }
}

__global__ void prep_kernel(const float* __restrict__ Wih1, const float* __restrict__ Whh1,
                            const float* __restrict__ bih1, const float* __restrict__ bhh1,
                            const float* __restrict__ Wih2, const float* __restrict__ Whh2,
                            const float* __restrict__ bih2, const float* __restrict__ bhh2) {
    int idx = blockIdx.x * blockDim.x + threadIdx.x;
    if (idx < NG * KK) {
        int r = idx >> 9, k = idx & 511;
        float w1 = (k < 256) ? Wih1[r * 256 + k] : Whh1[r * 256 + (k - 256)];
        g_W1[idx] = __float2half(w1);
        float w2 = (k < 256) ? Wih2[r * 256 + k] : Whh2[r * 256 + (k - 256)];
        g_W2[idx] = __float2half(w2);
    }
    if (idx < NG) {
        g_bias1[idx] = bih1[idx] + bhh1[idx];
        g_bias2[idx] = bih2[idx] + bhh2[idx];
    }
}

// ---------- encode ----------
__global__ void encode_kernel(const float* __restrict__ x, const float* __restrict__ W,
                              const float* __restrict__ b) {
    __shared__ float Ws[FF][HH];
    __shared__ float xs[32][FF];
    int tid = threadIdx.x;
    for (int idx = tid; idx < HH * FF; idx += 256) {
        int e = idx / FF, f = idx % FF;
        Ws[f][e] = W[idx];
    }
    long r0 = (long)blockIdx.x * 32;
    for (int idx = tid; idx < 32 * FF; idx += 256) {
        int r = idx / FF, f = idx % FF;
        xs[r][f] = x[(r0 + r) * FF + f];
    }
    __syncthreads();
    float be = b[tid];
    float acc[32];
    #pragma unroll
    for (int r = 0; r < 32; ++r) acc[r] = be;
    #pragma unroll
    for (int f = 0; f < FF; ++f) {
        float w = Ws[f][tid];
        #pragma unroll
        for (int r = 0; r < 32; ++r) acc[r] += xs[r][f] * w;
    }
    #pragma unroll
    for (int r = 0; r < 32; ++r) {
        long o = (r0 + r) * HH + tid;
        fp16 hi = __float2half(acc[r]);
        g_enc_hi[o] = hi;
        g_enc_lo[o] = __float2half(acc[r] - __half2float(hi));
    }
}

// ---------- fused LSTM cell (fp16 HMMA, 2 products, 512 thr, 3-stage, 1 sync/chunk,
//            register double-buffered fragments across k-steps) ----------
__device__ __forceinline__ void cell_load(char* stg, int ch, int tid, int m0, int u0,
                                          const fp16* __restrict__ Xhi, const fp16* __restrict__ Xlo,
                                          long xStride,
                                          const fp16* __restrict__ Hhi, const fp16* __restrict__ Hlo,
                                          const fp16* __restrict__ W) {
    const int r  = tid >> 2;             // smem row 0..127
    const int g0 = (tid & 3) << 1;       // first of two 16B granules
    const fp16 *Ah, *Al;
    if (ch < 4) { long o = (long)(m0 + r) * xStride + ch * 64; Ah = Xhi + o; Al = Xlo + o; }
    else        { long o = (long)(m0 + r) * HH + (ch - 4) * 64; Ah = Hhi + o; Al = Hlo + o; }
    const fp16* Bw = W + (long)(((r >> 5) << 8) + u0 + (r & 31)) * KK + ch * 64;
    char* row = stg + r * (PITCH * 2);
    #pragma unroll
    for (int j = 0; j < 2; ++j) {
        int g = g0 + j;
        int d = g << 4;
        cp16(row + d,               Ah + (g << 3));
        cp16(row + TILE_BB + d,     Al + (g << 3));
        cp16(row + 2 * TILE_BB + d, Bw + (g << 3));
    }
}

__device__ __forceinline__ void frag_load(const fp16* sAhi, const fp16* sAlo, const fp16* sBw,
                                          int ks, int wm, int wn, int lane,
                                          uint32_t ah[2][4], uint32_t al[2][4], uint32_t bw[4][2]) {
    #pragma unroll
    for (int mt = 0; mt < 2; ++mt) {
        int row = wm * 32 + mt * 16 + (lane & 15);
        int col = ks * 16 + ((lane >> 4) << 3);
        int o = row * PITCH + col;
        ldsm4(ah[mt][0], ah[mt][1], ah[mt][2], ah[mt][3], sAhi + o);
        ldsm4(al[mt][0], al[mt][1], al[mt][2], al[mt][3], sAlo + o);
    }
    #pragma unroll
    for (int np = 0; np < 2; ++np) {
        int row = wn * 32 + np * 16 + ((lane >> 4) << 3) + (lane & 7);
        int col = ks * 16 + (((lane >> 3) & 1) << 3);
        int o = row * PITCH + col;
        ldsm4(bw[2 * np][0], bw[2 * np][1], bw[2 * np + 1][0], bw[2 * np + 1][1], sBw + o);
    }
}

__device__ __forceinline__ void cell_compute(const fp16* sb, int wm, int wn, int lane,
                                             float acc[2][4][4]) {
    const fp16* sAhi = sb;
    const fp16* sAlo = sb + TILE_E;
    const fp16* sBw  = sb + 2 * TILE_E;
    // double-buffered fragments: ldsm for ks+1 issued before the MMAs of ks,
    // so HMMA work covers the ~30cyc ldsm result latency.
    uint32_t ah[2][2][4], al[2][2][4], bw[2][4][2];
    frag_load(sAhi, sAlo, sBw, 0, wm, wn, lane, ah[0], al[0], bw[0]);
    #pragma unroll
    for (int ks = 0; ks < 4; ++ks) {
        const int cur = ks & 1, nxt = cur ^ 1;
        if (ks < 3)
            frag_load(sAhi, sAlo, sBw, ks + 1, wm, wn, lane, ah[nxt], al[nxt], bw[nxt]);
        // per-acc order unchanged (hi product then lo product) -> bitwise-identical
        #pragma unroll
        for (int mt = 0; mt < 2; ++mt)
            #pragma unroll
            for (int nt = 0; nt < 4; ++nt)
                mma16816(acc[mt][nt], ah[cur][mt], bw[cur][nt]);
        #pragma unroll
        for (int mt = 0; mt < 2; ++mt)
            #pragma unroll
            for (int nt = 0; nt < 4; ++nt)
                mma16816(acc[mt][nt], al[cur][mt], bw[cur][nt]);
    }
}

__global__ void __launch_bounds__(512, 1)
cell_kernel(int layer, int xKind, int xIdx, int hIdx, int outIdx, int slot) {
    extern __shared__ __align__(128) char smem_raw[];
    const int tid  = threadIdx.x;
    const int wid  = tid >> 5;
    const int lane = tid & 31;
    const int wm   = wid & 3;
    const int wn   = wid >> 2;
    const int m0   = blockIdx.x * 128;
    const int u0   = blockIdx.y * 32;

    const fp16 *W, *Hhi, *Hlo;
    fp16 *HoHi, *HoLo;
    const float* bias;
    float* cSt;
    if (layer == 1) {
        W = g_W1; bias = g_bias1; cSt = g_c1;
        Hhi = g_h1_hi[hIdx]; Hlo = g_h1_lo[hIdx];
        HoHi = g_h1_hi[outIdx]; HoLo = g_h1_lo[outIdx];
    } else {
        W = g_W2; bias = g_bias2; cSt = g_c2;
        Hhi = g_h2_hi[hIdx]; Hlo = g_h2_lo[hIdx];
        HoHi = g_h2_hi[outIdx]; HoLo = g_h2_lo[outIdx];
    }
    const fp16 *Xhi, *Xlo;
    long xStride;
    if (xKind == 0)      { Xhi = g_enc_hi + (long)xIdx * HH; Xlo = g_enc_lo + (long)xIdx * HH; xStride = TT * HH; }
    else if (xKind == 1) { Xhi = g_h1_hi[xIdx]; Xlo = g_h1_lo[xIdx]; xStride = HH; }
    else                 { Xhi = g_h2_hi[xIdx]; Xlo = g_h2_lo[xIdx]; xStride = HH; }

    float acc[2][4][4];
    #pragma unroll
    for (int a = 0; a < 2; ++a)
        #pragma unroll
        for (int b = 0; b < 4; ++b)
            #pragma unroll
            for (int c = 0; c < 4; ++c) acc[a][b][c] = 0.f;

    // prologue: stages 0, 1 in flight
    cell_load(smem_raw + 0 * STAGE_B, 0, tid, m0, u0, Xhi, Xlo, xStride, Hhi, Hlo, W);
    cp_commit();
    cell_load(smem_raw + 1 * STAGE_B, 1, tid, m0, u0, Xhi, Xlo, xStride, Hhi, Hlo, W);
    cp_commit();

    // mainloop: ONE barrier per chunk.
    #pragma unroll 1
    for (int ch = 0; ch < 8; ++ch) {
        if (ch < 7) cp_wait1(); else cp_wait0();
        __syncthreads();
        if (ch + 2 < 8) {
            cell_load(smem_raw + ((ch + 2) % 3) * STAGE_B, ch + 2, tid, m0, u0,
                      Xhi, Xlo, xStride, Hhi, Hlo, W);
            cp_commit();
        }
        cell_compute((const fp16*)(smem_raw + (ch % 3) * STAGE_B), wm, wn, lane, acc);
    }
    __syncthreads();

    // epilogue: accumulators -> smem -> LSTM nonlinearity
    float* sAcc = (float*)smem_raw;
    const int PA = 132;
    #pragma unroll
    for (int mt = 0; mt < 2; ++mt)
        #pragma unroll
        for (int nt = 0; nt < 4; ++nt) {
            int row = wm * 32 + mt * 16 + (lane >> 2);
            int col = wn * 32 + nt * 8 + ((lane & 3) << 1);
            *(float2*)&sAcc[row * PA + col]       = make_float2(acc[mt][nt][0], acc[mt][nt][1]);
            *(float2*)&sAcc[(row + 8) * PA + col] = make_float2(acc[mt][nt][2], acc[mt][nt][3]);
        }
    __syncthreads();

    for (int idx = tid; idx < 128 * 32; idx += 512) {
        int row = idx >> 5, u = idx & 31;
        float iv = sAcc[row * PA + u]      + bias[u0 + u];
        float fv = sAcc[row * PA + 32 + u] + bias[256 + u0 + u];
        float gv = sAcc[row * PA + 64 + u] + bias[512 + u0 + u];
        float ov = sAcc[row * PA + 96 + u] + bias[768 + u0 + u];
        long gi = (long)(m0 + row) * HH + u0 + u;
        float c = fsig(fv) * cSt[gi] + fsig(iv) * ftanh(gv);
        cSt[gi] = c;
        float h = fsig(ov) * ftanh(c);
        fp16 hh = __float2half(h);
        HoHi[gi] = hh;
        HoLo[gi] = __float2half(h - __half2float(hh));
        if (slot >= 0)
            g_pred[((long)(m0 + row) * TT + slot) * HH + u0 + u] = h;
    }
}

// ---------- decode + cumsum + residual ----------
__global__ void dec_kernel(const float* __restrict__ x, const float* __restrict__ Wdec,
                           const float* __restrict__ bdec, float* __restrict__ out) {
    extern __shared__ float sm[];
    float* sP = sm;              // [64][260]
    float* sW = sm + 64 * 260;   // [34][260]
    int tid = threadIdx.x;
    long b0 = (long)blockIdx.x * 64;

    for (int i = tid; i < 34 * 64; i += 288) {
        int f = i / 64, k4 = i % 64;
        reinterpret_cast<float4*>(sW + f * 260)[k4] =
            reinterpret_cast<const float4*>(Wdec + f * 256)[k4];
    }

    int a = tid;
    bool act = a < 272;
    int rg = a & 15, fp = a >> 4;
    int f0 = fp * 2;
    float acc[4][2];
    float bd0 = 0.f, bd1 = 0.f;
    if (act) {
        bd0 = bdec[f0]; bd1 = bdec[f0 + 1];
        #pragma unroll
        for (int i = 0; i < 4; ++i) {
            long b = b0 + rg * 4 + i;
            acc[i][0] = x[b * (TT * FF) + 9 * FF + f0];
            acc[i][1] = x[b * (TT * FF) + 9 * FF + f0 + 1];
        }
    }

    #pragma unroll 1
    for (int j = 0; j < TT; ++j) {
        __syncthreads();
        for (int i = tid; i < 64 * 64; i += 288) {
            int r = i >> 6, k4 = i & 63;
            reinterpret_cast<float4*>(sP + r * 260)[k4] =
                reinterpret_cast<const float4*>(g_pred + (b0 + r) * (TT * HH) + j * HH)[k4];
        }
        __syncthreads();
        if (act) {
            float s[4][2] = {{0.f, 0.f}, {0.f, 0.f}, {0.f, 0.f}, {0.f, 0.f}};
            #pragma unroll 4
            for (int k = 0; k < 256; k += 4) {
                float4 w0 = *reinterpret_cast<float4*>(sW + f0 * 260 + k);
                float4 w1 = *reinterpret_cast<float4*>(sW + (f0 + 1) * 260 + k);
                #pragma unroll
                for (int i = 0; i < 4; ++i) {
                    float4 p = *reinterpret_cast<float4*>(sP + (rg * 4 + i) * 260 + k);
                    s[i][0] += p.x * w0.x + p.y * w0.y + p.z * w0.z + p.w * w0.w;
                    s[i][1] += p.x * w1.x + p.y * w1.y + p.z * w1.z + p.w * w1.w;
                }
            }
            #pragma unroll
            for (int i = 0; i < 4; ++i) {
                acc[i][0] += s[i][0] + bd0;
                acc[i][1] += s[i][1] + bd1;
                long b = b0 + rg * 4 + i;
                out[b * (TT * FF) + j * FF + f0]     = acc[i][0];
                out[b * (TT * FF) + j * FF + f0 + 1] = acc[i][1];
            }
        }
    }
}

// ---------- launch ----------
extern "C" void kernel_launch(void* const* d_in, const int* in_sizes, int n_in,
                              void* d_out, int out_size) {
    const float* x     = (const float*)d_in[0];
    const float* W_enc = (const float*)d_in[1];
    const float* b_enc = (const float*)d_in[2];
    const float* Wih1  = (const float*)d_in[3];
    const float* Whh1  = (const float*)d_in[4];
    const float* bih1  = (const float*)d_in[5];
    const float* bhh1  = (const float*)d_in[6];
    const float* Wih2  = (const float*)d_in[7];
    const float* Whh2  = (const float*)d_in[8];
    const float* bih2  = (const float*)d_in[9];
    const float* bhh2  = (const float*)d_in[10];
    const float* Wdec  = (const float*)d_in[11];
    const float* bdec  = (const float*)d_in[12];
    float* out = (float*)d_out;

    cudaFuncSetAttribute(cell_kernel, cudaFuncAttributeMaxDynamicSharedMemorySize, SMEM_CELL);
    cudaFuncSetAttribute(dec_kernel,  cudaFuncAttributeMaxDynamicSharedMemorySize, SMEM_DEC);

    zero_state_kernel<<<(BATCH * HH + 255) / 256, 256>>>();
    prep_kernel<<<(NG * KK + 255) / 256, 256>>>(Wih1, Whh1, bih1, bhh1, Wih2, Whh2, bih2, bhh2);
    encode_kernel<<<(BATCH * TT) / 32, 256>>>(x, W_enc, b_enc);

    dim3 cg(BATCH / 128, HH / 32);
    int p1 = 0, p2 = 0;
    for (int t = 0; t < TT; ++t) {
        cell_kernel<<<cg, 512, SMEM_CELL>>>(1, 0, t, p1, p1 ^ 1, -1);
        p1 ^= 1;
        cell_kernel<<<cg, 512, SMEM_CELL>>>(2, 1, p1, p2, p2 ^ 1, (t == 9) ? 0 : -1);
        p2 ^= 1;
    }
    for (int s = 1; s <= 9; ++s) {
        cell_kernel<<<cg, 512, SMEM_CELL>>>(1, 2, p2, p1, p1 ^ 1, -1);
        p1 ^= 1;
        cell_kernel<<<cg, 512, SMEM_CELL>>>(2, 1, p1, p2, p2 ^ 1, s);
        p2 ^= 1;
    }
    dec_kernel<<<BATCH / 64, 288, SMEM_DEC>>>(x, Wdec, bdec, out);
}